// round 11
// baseline (speedup 1.0000x reference)
#include <cuda_runtime.h>
#include <cuda_fp16.h>
#include <cstdint>

// ============================================================================
// z_{k+1} = tanh(z_k @ W^T + b + x), 25 fixed iterations.
// Transposed persistent GEMM: D[feat, batch] = W[feat,k] @ z^T[k,batch].
//   - W in REGISTERS (128 regs/thread via one-time ldmatrix) -> no W traffic.
//   - z in SMEM, batch rows at 528B stride (conflict-free ldmatrix reads AND
//     conflict-free u16 epilogue stores; no XOR swizzle needed), double-buffered.
//   - x read row-major from L2, PREFETCHED into regs before each chunk's GEMM.
//   - bias in registers. One __syncthreads per iteration. it==0 skips GEMM.
// ============================================================================

#define NT     256
#define NB     256
#define ITERS  25
#define BATCH  32768
#define F      256
#define ZSTRIDE 528                    // 132 words = 4 mod 32 banks
#define ZBUF   (128 * ZSTRIDE)         // 67584 B
#define SMEM_TOTAL (2 * ZBUF)          // 135168 B (also W staging space)

__device__ __forceinline__ uint32_t smem_u32(const void* p) {
    uint32_t a;
    asm("{ .reg .u64 t; cvta.to.shared.u64 t, %1; cvt.u32.u64 %0, t; }"
        : "=r"(a) : "l"(p));
    return a;
}

__device__ __forceinline__ float tanh_fast(float u) {
    float e, r;
    asm("ex2.approx.f32 %0, %1;" : "=f"(e) : "f"(u * 2.885390081777927f));
    asm("rcp.approx.f32 %0, %1;" : "=f"(r) : "f"(e + 1.0f));
    return fmaf(-2.0f, r, 1.0f);
}

__device__ __forceinline__ void mma16816(float* d, const uint32_t* a,
                                         uint32_t b0, uint32_t b1) {
    asm volatile(
        "mma.sync.aligned.m16n8k16.row.col.f32.f16.f16.f32 "
        "{%0,%1,%2,%3}, {%4,%5,%6,%7}, {%8,%9}, {%0,%1,%2,%3};"
        : "+f"(d[0]), "+f"(d[1]), "+f"(d[2]), "+f"(d[3])
        : "r"(a[0]), "r"(a[1]), "r"(a[2]), "r"(a[3]), "r"(b0), "r"(b1));
}

__device__ __forceinline__ void ldsm4(uint32_t* r, uint32_t addr) {
    asm volatile("ldmatrix.sync.aligned.m8n8.x4.shared.b16 {%0,%1,%2,%3}, [%4];"
                 : "=r"(r[0]), "=r"(r[1]), "=r"(r[2]), "=r"(r[3]) : "r"(addr));
}

__device__ __forceinline__ void sts16(uint32_t addr, float v) {
    const unsigned short h = __half_as_ushort(__float2half_rn(v));
    asm volatile("st.shared.u16 [%0], %1;" :: "r"(addr), "h"(h) : "memory");
}

__global__ void __launch_bounds__(NT, 1)
fp_kernel(float* __restrict__ out, const float* __restrict__ x,
          const float* __restrict__ W, const float* __restrict__ bias) {
    extern __shared__ char smem[];
    const uint32_t sS = smem_u32(smem);
    const int tid = threadIdx.x, lane = tid & 31, warp = tid >> 5;
    const int g = lane >> 2, tig = lane & 3;

    // ---- stage W fp16 (512B rows + XOR swizzle, one-time) then -> A regs ----
    {
        const float2* W2 = reinterpret_cast<const float2*>(W);
        for (int idx = tid; idx < F * (F / 2); idx += NT) {
            const int n = idx >> 7;
            const float2 w = W2[idx];
            uint32_t off = (uint32_t)(n * 512 + (idx & 127) * 4);
            off ^= (uint32_t)((n & 7) << 4);
            *reinterpret_cast<__half2*>(smem + off) = __floats2half2_rn(w.x, w.y);
        }
    }
    __syncthreads();

    uint32_t a[128];                     // W A-fragments: [mt 2][c 16][r 4]
    {
        const uint32_t xorv = (uint32_t)((lane & 7) << 4);
        const int m_lane = (lane & 7) | (((lane >> 3) & 1) << 3);
        const uint32_t k_seg = (uint32_t)(((lane >> 4) & 1) * 16);
        const int wfeat = warp * 32;
        #pragma unroll
        for (int mt = 0; mt < 2; ++mt)
            #pragma unroll
            for (int c = 0; c < 16; ++c) {
                const uint32_t addr = sS
                    + (uint32_t)((wfeat + mt * 16 + m_lane) * 512)
                    + (((uint32_t)(c * 32) + k_seg) ^ xorv);
                ldsm4(&a[(mt * 16 + c) * 4], addr);
            }
    }
    __syncthreads();                     // staging now reusable as z buffers

    // ---- per-thread geometry ------------------------------------------------
    const int fg0 = warp * 32 + g;       // feat rows: fg0(+8) [mt0], fg0+16(+24) [mt1]
    const int bb_cta = blockIdx.x * 128;
    float bia[4];                        // bias[fg0], [+8], [+16], [+24]
    bia[0] = bias[fg0];      bia[1] = bias[fg0 + 8];
    bia[2] = bias[fg0 + 16]; bia[3] = bias[fg0 + 24];

    // z ldmatrix lane groups (batch rows): 0-7 n0-7/klo, 8-15 n0-7/khi,
    // 16-23 n8-15/klo, 24-31 n8-15/khi
    const int n_lane = (lane & 7) + ((lane >> 4) << 3);
    const uint32_t lane_k = (uint32_t)(((lane >> 3) & 1) * 16);

    #pragma unroll 1
    for (int it = 0; it < ITERS; ++it) {
        const uint32_t zw = sS + (uint32_t)((it & 1) * ZBUF);
        const uint32_t zr = sS + (uint32_t)(((it & 1) ^ 1) * ZBUF);
        const bool last = (it == ITERS - 1);

        #pragma unroll
        for (int nc = 0; nc < 4; ++nc) {             // 4 batch chunks of 32
            // ---- prefetch x (row-major, L2-hot) for this chunk --------------
            float xr[32];                            // [mt2][nt4][4]
            #pragma unroll
            for (int mt = 0; mt < 2; ++mt)
                #pragma unroll
                for (int nt = 0; nt < 4; ++nt) {
                    const int bl = nc * 32 + nt * 8 + tig * 2;
                    const int fg = fg0 + mt * 16;
                    const float* xp = x + (size_t)(bb_cta + bl) * F + fg;
                    const int q = (mt * 4 + nt) * 4;
                    xr[q + 0] = xp[0];       // (b,   fg)
                    xr[q + 1] = xp[F];       // (b+1, fg)
                    xr[q + 2] = xp[8];       // (b,   fg+8)
                    xr[q + 3] = xp[F + 8];   // (b+1, fg+8)
                }

            // ---- GEMM chunk (skipped at it==0: z0 = 0) ----------------------
            float d[32];
            #pragma unroll
            for (int i = 0; i < 32; ++i) d[i] = 0.0f;
            if (it) {
                #pragma unroll
                for (int c = 0; c < 16; ++c) {
                    uint32_t bf[8];
                    #pragma unroll
                    for (int ntp = 0; ntp < 2; ++ntp)
                        ldsm4(&bf[ntp * 4],
                              zr + (uint32_t)((nc * 32 + ntp * 16 + n_lane) * ZSTRIDE)
                                 + (lane_k + (uint32_t)(c * 32)));
                    #pragma unroll
                    for (int mt = 0; mt < 2; ++mt)
                        #pragma unroll
                        for (int nt = 0; nt < 4; ++nt) {
                            const int bi = (nt >> 1) * 4 + (nt & 1) * 2;
                            mma16816(&d[(mt * 4 + nt) * 4],
                                     &a[(mt * 16 + c) * 4], bf[bi], bf[bi + 1]);
                        }
                }
            }

            // ---- epilogue: z_new = tanh(D + b + x) --------------------------
            #pragma unroll
            for (int mt = 0; mt < 2; ++mt)
                #pragma unroll
                for (int nt = 0; nt < 4; ++nt) {
                    const int fg = fg0 + mt * 16;
                    const int bl = nc * 32 + nt * 8 + tig * 2;
                    const int bglob = bb_cta + bl;
                    const float* dd = &d[(mt * 4 + nt) * 4];
                    const float* xq = &xr[(mt * 4 + nt) * 4];
                    const float b0 = bia[mt * 2], b1 = bia[mt * 2 + 1];
                    const float t0 = tanh_fast(dd[0] + b0 + xq[0]); // (fg,  b)
                    const float t1 = tanh_fast(dd[1] + b0 + xq[1]); // (fg,  b+1)
                    const float t2 = tanh_fast(dd[2] + b1 + xq[2]); // (fg+8,b)
                    const float t3 = tanh_fast(dd[3] + b1 + xq[3]); // (fg+8,b+1)
                    if (!last) {
                        const uint32_t r0 = zw + (uint32_t)(bl * ZSTRIDE + fg * 2);
                        const uint32_t r1 = r0 + ZSTRIDE;
                        sts16(r0, t0);
                        sts16(r1, t1);
                        sts16(r0 + 16, t2);          // feat+8 = +16B in-row
                        sts16(r1 + 16, t3);
                    } else {
                        out[(size_t)bglob * F + fg]           = t0;
                        out[(size_t)(bglob + 1) * F + fg]     = t1;
                        out[(size_t)bglob * F + fg + 8]       = t2;
                        out[(size_t)(bglob + 1) * F + fg + 8] = t3;
                    }
                }
        }
        __syncthreads();   // publish zw; zr free for next iteration's writes
    }
}

// ----------------------------------------------------------------------------
extern "C" void kernel_launch(void* const* d_in, const int* in_sizes, int n_in,
                              void* d_out, int out_size) {
    const float* x = nullptr;
    const float* W = nullptr;
    const float* b = nullptr;
    for (int i = 0; i < n_in; ++i) {
        if (in_sizes[i] == BATCH * F)   x = (const float*)d_in[i];
        else if (in_sizes[i] == F * F)  W = (const float*)d_in[i];
        else if (in_sizes[i] == F)      b = (const float*)d_in[i];
    }
    if (!x && n_in > 0) x = (const float*)d_in[0];
    if (!W && n_in > 1) W = (const float*)d_in[1];
    if (!b && n_in > 2) b = (const float*)d_in[2];

    static int once = 0;
    if (!once) {
        cudaFuncSetAttribute(fp_kernel,
                             cudaFuncAttributeMaxDynamicSharedMemorySize,
                             SMEM_TOTAL);
        once = 1;
    }
    fp_kernel<<<NB, NT, SMEM_TOTAL>>>((float*)d_out, x, W, b);
}

// round 12
// speedup vs baseline: 1.0542x; 1.0542x over previous
#include <cuda_runtime.h>
#include <cuda_fp16.h>
#include <cstdint>

// ============================================================================
// z_{k+1} = tanh(z_k @ W^T + b + x), 25 fixed iterations.
// R5 orientation (validated): D[batch, feat] = z @ W^T; A = z fragments in
// registers, B = W fp16 in SMEM via ldmatrix.
// R12 changes:
//   - m = 32 rows/warp (was 16) -> 256 rows/CTA -> 128 CTAs = SINGLE WAVE.
//     W smem traffic per warp is m-independent, so arithmetic intensity 2x.
//   - z_new staging moved from 64 registers to a 16 MB __device__ buffer,
//     spilled/reloaded in each thread's OWN fragment layout (the D->A remap
//     is thread-local, proven in R5). Same-thread STG->LDG needs no fences.
//   - ZERO __syncthreads in the iteration loop; warps drift -> MUFU epilogue
//     overlaps other warps' HMMA on the same SMSP.
//   - n-chunks of 32 (8 chunks): d[32] regs, za[128] regs, bf[8]. ~190 regs.
// ============================================================================

#define NT     256
#define NB     128
#define ITERS  25
#define BATCH  32768
#define F      256
#define SMEM_BOFF (256 * 512)
#define SMEM_TOTAL (256 * 512 + 256 * 4)   // W 128KB + bias 1KB

__device__ uint2 g_z[(size_t)NB * NT * 64];   // 512 B per thread, 16 MB total

__device__ __forceinline__ uint32_t smem_u32(const void* p) {
    uint32_t a;
    asm("{ .reg .u64 t; cvta.to.shared.u64 t, %1; cvt.u32.u64 %0, t; }"
        : "=r"(a) : "l"(p));
    return a;
}

__device__ __forceinline__ float tanh_fast(float u) {
    float e, r;
    asm("ex2.approx.f32 %0, %1;" : "=f"(e) : "f"(u * 2.885390081777927f));
    asm("rcp.approx.f32 %0, %1;" : "=f"(r) : "f"(e + 1.0f));
    return fmaf(-2.0f, r, 1.0f);
}

__device__ __forceinline__ uint32_t pack2(float lo, float hi) {
    uint32_t r;
    asm("cvt.rn.f16x2.f32 %0, %1, %2;" : "=r"(r) : "f"(hi), "f"(lo));
    return r;
}

__device__ __forceinline__ void mma16816(float* d, const uint32_t* a,
                                         uint32_t b0, uint32_t b1) {
    asm volatile(
        "mma.sync.aligned.m16n8k16.row.col.f32.f16.f16.f32 "
        "{%0,%1,%2,%3}, {%4,%5,%6,%7}, {%8,%9}, {%0,%1,%2,%3};"
        : "+f"(d[0]), "+f"(d[1]), "+f"(d[2]), "+f"(d[3])
        : "r"(a[0]), "r"(a[1]), "r"(a[2]), "r"(a[3]), "r"(b0), "r"(b1));
}

__device__ __forceinline__ void ldsm4(uint32_t* r, uint32_t addr) {
    asm volatile("ldmatrix.sync.aligned.m8n8.x4.shared.b16 {%0,%1,%2,%3}, [%4];"
                 : "=r"(r[0]), "=r"(r[1]), "=r"(r[2]), "=r"(r[3]) : "r"(addr));
}

__global__ void __launch_bounds__(NT, 1)
fp_kernel(float* __restrict__ out, const float* __restrict__ x,
          const float* __restrict__ W, const float* __restrict__ bias) {
    extern __shared__ char smem[];
    const uint32_t sW = smem_u32(smem);
    float* bs = reinterpret_cast<float*>(smem + SMEM_BOFF);

    const int tid = threadIdx.x, lane = tid & 31, warp = tid >> 5;
    const int g = lane >> 2, tig = lane & 3;

    // ---- stage W fp16 (512B rows, XOR swizzle) — identical to R5 -----------
    {
        const float2* W2 = reinterpret_cast<const float2*>(W);
        for (int idx = tid; idx < F * (F / 2); idx += NT) {
            const int n = idx >> 7;
            const float2 w = W2[idx];
            uint32_t off = (uint32_t)(n * 512 + (idx & 127) * 4);
            off ^= (uint32_t)((n & 7) << 4);
            *reinterpret_cast<__half2*>(smem + off) = __floats2half2_rn(w.x, w.y);
        }
        bs[tid] = bias[tid];
    }
    __syncthreads();            // the only block sync in the kernel

    // ---- geometry -----------------------------------------------------------
    // W (B operand) ldmatrix lane groups: 0-7 n0-7/klo, 8-15 n0-7/khi,
    // 16-23 n8-15/klo, 24-31 n8-15/khi  (validated in R5)
    const int n_lane = (lane & 7) + ((lane >> 4) << 3);
    const uint32_t lane_k = (uint32_t)(((lane >> 3) & 1) * 16);
    const uint32_t xorv = (uint32_t)((lane & 7) << 4);
    const int bbw = blockIdx.x * 256 + warp * 32;   // warp's batch-row base
    uint2* zth = g_z + ((size_t)blockIdx.x * NT + tid) * 64;

    // z as A-fragments (fp16x2): za[mt*64 + c*4 + r], mt in {0,1} (rows
    // +0/+8 and +16/+24), c = k-tile 0..15, r = standard A order
    // [klo-g, klo-g8, khi-g, khi-g8].
    uint32_t za[128];
    #pragma unroll
    for (int i = 0; i < 128; ++i) za[i] = 0u;

    #pragma unroll 1
    for (int it = 0; it < ITERS; ++it) {
        const bool last = (it == ITERS - 1);

        if (it) {   // reload this thread's z fragments (written by itself)
            const uint4* zl = reinterpret_cast<const uint4*>(zth);
            #pragma unroll
            for (int q = 0; q < 32; ++q) {
                const uint4 v = zl[q];
                za[q * 4 + 0] = v.x; za[q * 4 + 1] = v.y;
                za[q * 4 + 2] = v.z; za[q * 4 + 3] = v.w;
            }
        }

        #pragma unroll
        for (int nc = 0; nc < 8; ++nc) {            // 8 feat chunks of 32
            float d[32];                            // [mt2][nt4][4]
            #pragma unroll
            for (int i = 0; i < 32; ++i) d[i] = 0.0f;

            if (it) {
                #pragma unroll
                for (int c = 0; c < 16; ++c) {      // k-tiles
                    uint32_t bf[8];
                    #pragma unroll
                    for (int ntp = 0; ntp < 2; ++ntp)
                        ldsm4(&bf[ntp * 4],
                              sW + (uint32_t)((nc * 32 + ntp * 16 + n_lane) * 512)
                                 + ((lane_k + (uint32_t)(c * 32)) ^ xorv));
                    #pragma unroll
                    for (int mt = 0; mt < 2; ++mt)
                        #pragma unroll
                        for (int nt = 0; nt < 4; ++nt)
                            mma16816(&d[(mt * 4 + nt) * 4],
                                     &za[mt * 64 + c * 4],
                                     bf[nt * 2], bf[nt * 2 + 1]);
                }
            }

            // ---- epilogue: z_new = tanh(D + b + x) --------------------------
            #pragma unroll
            for (int mt = 0; mt < 2; ++mt)
                #pragma unroll
                for (int nt = 0; nt < 4; ++nt) {
                    const int n = nc * 32 + nt * 8 + tig * 2;   // feat pair
                    const int bg = bbw + mt * 16 + g;           // batch row
                    const float* dd = &d[(mt * 4 + nt) * 4];
                    const float2 bb = *reinterpret_cast<const float2*>(bs + n);
                    const float2 xa = *reinterpret_cast<const float2*>(
                        x + (size_t)bg * F + n);
                    const float2 xb = *reinterpret_cast<const float2*>(
                        x + (size_t)(bg + 8) * F + n);
                    const float t0 = tanh_fast(dd[0] + bb.x + xa.x); // (bg,  n)
                    const float t1 = tanh_fast(dd[1] + bb.y + xa.y); // (bg,  n+1)
                    const float t2 = tanh_fast(dd[2] + bb.x + xb.x); // (bg+8,n)
                    const float t3 = tanh_fast(dd[3] + bb.y + xb.y); // (bg+8,n+1)
                    if (!last) {
                        // feat n -> next-iter k: k-tile c = n>>4, half h = nt&1.
                        // uint2 = regs {h*2, h*2+1} = rows g / g+8 at this k-half.
                        const int c = nc * 2 + (nt >> 1), h = nt & 1;
                        zth[mt * 32 + c * 2 + h] =
                            make_uint2(pack2(t0, t1), pack2(t2, t3));
                    } else {
                        *reinterpret_cast<float2*>(out + (size_t)bg * F + n) =
                            make_float2(t0, t1);
                        *reinterpret_cast<float2*>(out + (size_t)(bg + 8) * F + n) =
                            make_float2(t2, t3);
                    }
                }
        }
        // no barrier: each thread re-reads only its own g_z bytes next iter
    }
}

// ----------------------------------------------------------------------------
extern "C" void kernel_launch(void* const* d_in, const int* in_sizes, int n_in,
                              void* d_out, int out_size) {
    const float* x = nullptr;
    const float* W = nullptr;
    const float* b = nullptr;
    for (int i = 0; i < n_in; ++i) {
        if (in_sizes[i] == BATCH * F)   x = (const float*)d_in[i];
        else if (in_sizes[i] == F * F)  W = (const float*)d_in[i];
        else if (in_sizes[i] == F)      b = (const float*)d_in[i];
    }
    if (!x && n_in > 0) x = (const float*)d_in[0];
    if (!W && n_in > 1) W = (const float*)d_in[1];
    if (!b && n_in > 2) b = (const float*)d_in[2];

    static int once = 0;
    if (!once) {
        cudaFuncSetAttribute(fp_kernel,
                             cudaFuncAttributeMaxDynamicSharedMemorySize,
                             SMEM_TOTAL);
        once = 1;
    }
    fp_kernel<<<NB, NT, SMEM_TOTAL>>>((float*)d_out, x, W, b);
}

// round 15
// speedup vs baseline: 1.7859x; 1.6941x over previous
#include <cuda_runtime.h>
#include <cuda_fp16.h>
#include <cstdint>

// ============================================================================
// z_{k+1} = tanh(z_k @ W^T + b + x), 25 fixed iterations.
// R5 structure (validated, 404us): D[batch,feat] = z @ W^T; A = z fragments
// in registers; B = W fp16 in SMEM streamed via ldmatrix; 256 CTAs x 128 rows.
// R13 deltas (latency removal, math identical):
//   1. z_new staging moved from 64 regs to SMEM (thread-interleaved, same-
//      thread write/read -> no sync). Frees 64 regs for scheduling.
//   2. bf double-buffer: ldsm for k-tile c+1 prefetched under c's 8 HMMA.
//   3. x prefetched into regs per n-chunk BEFORE the GEMM (hides L2 latency).
// ============================================================================

#define NT     256
#define NB     256
#define ITERS  25
#define BATCH  32768
#define F      256
#define SMEM_W    0
#define SMEM_BOFF (256 * 512)                    // bias after W (128 KB)
#define SMEM_ZOFF (256 * 512 + 1024)             // zn staging: 64 KB
#define SMEM_TOTAL (256 * 512 + 1024 + 65536)    // 197632 B

__device__ __forceinline__ uint32_t smem_u32(const void* p) {
    uint32_t a;
    asm("{ .reg .u64 t; cvta.to.shared.u64 t, %1; cvt.u32.u64 %0, t; }"
        : "=r"(a) : "l"(p));
    return a;
}

__device__ __forceinline__ float tanh_fast(float u) {
    float e, r;
    asm("ex2.approx.f32 %0, %1;" : "=f"(e) : "f"(u * 2.885390081777927f));
    asm("rcp.approx.f32 %0, %1;" : "=f"(r) : "f"(e + 1.0f));
    return fmaf(-2.0f, r, 1.0f);
}

__device__ __forceinline__ uint32_t pack2(float lo, float hi) {
    uint32_t r;
    asm("cvt.rn.f16x2.f32 %0, %1, %2;" : "=r"(r) : "f"(hi), "f"(lo));
    return r;
}

__device__ __forceinline__ void mma16816(float* d, const uint32_t* a,
                                         uint32_t b0, uint32_t b1) {
    asm volatile(
        "mma.sync.aligned.m16n8k16.row.col.f32.f16.f16.f32 "
        "{%0,%1,%2,%3}, {%4,%5,%6,%7}, {%8,%9}, {%0,%1,%2,%3};"
        : "+f"(d[0]), "+f"(d[1]), "+f"(d[2]), "+f"(d[3])
        : "r"(a[0]), "r"(a[1]), "r"(a[2]), "r"(a[3]), "r"(b0), "r"(b1));
}

__device__ __forceinline__ void ldsm4(uint32_t* r, uint32_t addr) {
    asm volatile("ldmatrix.sync.aligned.m8n8.x4.shared.b16 {%0,%1,%2,%3}, [%4];"
                 : "=r"(r[0]), "=r"(r[1]), "=r"(r[2]), "=r"(r[3]) : "r"(addr));
}

__global__ void __launch_bounds__(NT, 1)
fp_kernel(float* __restrict__ out, const float* __restrict__ x,
          const float* __restrict__ W, const float* __restrict__ bias) {
    extern __shared__ char smem[];
    const uint32_t sW = smem_u32(smem);
    float* bs = reinterpret_cast<float*>(smem + SMEM_BOFF);
    uint32_t* zs = reinterpret_cast<uint32_t*>(smem + SMEM_ZOFF);

    const int tid = threadIdx.x, lane = tid & 31, warp = tid >> 5;
    const int g = lane >> 2, tig = lane & 3;

    // ---- stage W fp16 (512B rows, XOR swizzle) — identical to R5 -----------
    {
        const float2* W2 = reinterpret_cast<const float2*>(W);
        for (int idx = tid; idx < F * (F / 2); idx += NT) {
            const int n = idx >> 7;
            const float2 w = W2[idx];
            uint32_t off = (uint32_t)(n * 512 + (idx & 127) * 4);
            off ^= (uint32_t)((n & 7) << 4);
            *reinterpret_cast<__half2*>(smem + off) = __floats2half2_rn(w.x, w.y);
        }
        bs[tid] = bias[tid];
    }
    __syncthreads();            // the only block sync in the kernel

    // ---- geometry (identical to R5) ----------------------------------------
    const int n_lane = (lane & 7) + ((lane >> 4) << 3);
    const uint32_t lane_k = (uint32_t)(((lane >> 3) & 1) * 16);
    const uint32_t xorv = (uint32_t)((lane & 7) << 4);
    const uint32_t lbase = sW + (uint32_t)(n_lane * 512);
    const size_t m0 = (size_t)blockIdx.x * 128 + warp * 16 + g;
    const float* x0 = x + m0 * 256;
    const float* x1 = x0 + 8 * 256;
    float* o0 = out + m0 * 256;
    float* o1 = o0 + 8 * 256;

    uint32_t za[64];            // z A-fragments: [c 16][4]
    #pragma unroll
    for (int i = 0; i < 64; ++i) za[i] = 0u;

    #pragma unroll 1
    for (int it = 0; it < ITERS; ++it) {
        const bool last = (it == ITERS - 1);

        if (it) {               // reload own fragments from staging (no sync
            #pragma unroll      // needed: same-thread write -> read)
            for (int q = 0; q < 64; ++q)
                za[q] = zs[q * NT + tid];
        }

        #pragma unroll
        for (int nc = 0; nc < 4; ++nc) {            // 4 feat chunks of 64
            // ---- prefetch x for this chunk (hidden under GEMM) --------------
            float2 xA[8], xB[8];
            #pragma unroll
            for (int nt = 0; nt < 8; ++nt) {
                const int n = nc * 64 + nt * 8 + tig * 2;
                xA[nt] = *reinterpret_cast<const float2*>(x0 + n);
                xB[nt] = *reinterpret_cast<const float2*>(x1 + n);
            }

            float d[32];
            #pragma unroll
            for (int i = 0; i < 32; ++i) d[i] = 0.0f;

            if (it) {                               // it==0: z = 0, skip GEMM
                const uint32_t cb = lbase + (uint32_t)(nc * 64 * 512);
                uint32_t bf[2][16];
                #pragma unroll
                for (int ntp = 0; ntp < 4; ++ntp)   // preload k-tile 0
                    ldsm4(&bf[0][ntp * 4],
                          cb + (uint32_t)(ntp * 8192) + (lane_k ^ xorv));
                #pragma unroll
                for (int c = 0; c < 16; ++c) {
                    const int cur = c & 1;
                    if (c < 15) {                   // prefetch k-tile c+1
                        #pragma unroll
                        for (int ntp = 0; ntp < 4; ++ntp)
                            ldsm4(&bf[cur ^ 1][ntp * 4],
                                  cb + (uint32_t)(ntp * 8192)
                                     + ((lane_k + (uint32_t)((c + 1) * 32)) ^ xorv));
                    }
                    #pragma unroll
                    for (int nt = 0; nt < 8; ++nt) {
                        const int bi = (nt >> 1) * 4 + (nt & 1) * 2;
                        mma16816(&d[nt * 4], &za[c * 4],
                                 bf[cur][bi], bf[cur][bi + 1]);
                    }
                }
            }

            // ---- epilogue: z_new = tanh(D + b + x) --------------------------
            #pragma unroll
            for (int nt = 0; nt < 8; ++nt) {
                const int n = nc * 64 + nt * 8 + tig * 2;
                const float2 bb = *reinterpret_cast<const float2*>(bs + n);
                const float* dd = &d[nt * 4];
                const float t0 = tanh_fast(dd[0] + bb.x + xA[nt].x);
                const float t1 = tanh_fast(dd[1] + bb.y + xA[nt].y);
                const float t2 = tanh_fast(dd[2] + bb.x + xB[nt].x);
                const float t3 = tanh_fast(dd[3] + bb.y + xB[nt].y);
                if (!last) {
                    // feat n -> next-iter A k-tile (validated R5 remap):
                    // ci = (nc*4 + nt/2)*4 + (nt&1)*2; slots ci (rows g),
                    // ci+1 (rows g+8), thread-interleaved in SMEM.
                    const int ci = (nc * 4 + (nt >> 1)) * 4 + (nt & 1) * 2;
                    zs[ci * NT + tid]       = pack2(t0, t1);
                    zs[(ci + 1) * NT + tid] = pack2(t2, t3);
                } else {
                    *reinterpret_cast<float2*>(o0 + n) = make_float2(t0, t1);
                    *reinterpret_cast<float2*>(o1 + n) = make_float2(t2, t3);
                }
            }
        }
        // no barrier: each thread re-reads only its own zs slots next iter
    }
}

// ----------------------------------------------------------------------------
extern "C" void kernel_launch(void* const* d_in, const int* in_sizes, int n_in,
                              void* d_out, int out_size) {
    const float* x = nullptr;
    const float* W = nullptr;
    const float* b = nullptr;
    for (int i = 0; i < n_in; ++i) {
        if (in_sizes[i] == BATCH * F)   x = (const float*)d_in[i];
        else if (in_sizes[i] == F * F)  W = (const float*)d_in[i];
        else if (in_sizes[i] == F)      b = (const float*)d_in[i];
    }
    if (!x && n_in > 0) x = (const float*)d_in[0];
    if (!W && n_in > 1) W = (const float*)d_in[1];
    if (!b && n_in > 2) b = (const float*)d_in[2];

    static int once = 0;
    if (!once) {
        cudaFuncSetAttribute(fp_kernel,
                             cudaFuncAttributeMaxDynamicSharedMemorySize,
                             SMEM_TOTAL);
        once = 1;
    }
    fp_kernel<<<NB, NT, SMEM_TOTAL>>>((float*)d_out, x, W, b);
}

// round 16
// speedup vs baseline: 2.0692x; 1.1586x over previous
#include <cuda_runtime.h>
#include <cuda_fp16.h>
#include <cstdint>

// ============================================================================
// z_{k+1} = tanh(z_k @ W^T + b + x), 25 fixed iterations.
// R5/R15 structure (validated, 404us): D[batch,feat] = z @ W^T; A = z frags
// in registers; B = W fp16 in SMEM via ldmatrix (double-buffered); zn staged
// in SMEM (same-thread rw, no sync); 256 CTAs x 128 rows.
// R16 deltas (epilogue-throughput attack, GEMM math identical):
//   1. tanh.approx.f32 (1 MUFU/elt, was ex2+rcp = 2 MUFU + 2 FMA).
//   2. b + x folded into the accumulator INIT (d = b+x before GEMM) -> the
//      adds ride under HMMA; epilogue is tanh+pack+store only. Also unifies
//      the it==0 skip-GEMM path (tanh(b+x) falls out naturally).
// ============================================================================

#define NT     256
#define NB     256
#define ITERS  25
#define BATCH  32768
#define F      256
#define SMEM_W    0
#define SMEM_BOFF (256 * 512)                    // bias after W (128 KB)
#define SMEM_ZOFF (256 * 512 + 1024)             // zn staging: 64 KB
#define SMEM_TOTAL (256 * 512 + 1024 + 65536)    // 197632 B

__device__ __forceinline__ uint32_t smem_u32(const void* p) {
    uint32_t a;
    asm("{ .reg .u64 t; cvta.to.shared.u64 t, %1; cvt.u32.u64 %0, t; }"
        : "=r"(a) : "l"(p));
    return a;
}

__device__ __forceinline__ float tanh_approx(float u) {
    float r;
    asm("tanh.approx.f32 %0, %1;" : "=f"(r) : "f"(u));
    return r;
}

__device__ __forceinline__ uint32_t pack2(float lo, float hi) {
    uint32_t r;
    asm("cvt.rn.f16x2.f32 %0, %1, %2;" : "=r"(r) : "f"(hi), "f"(lo));
    return r;
}

__device__ __forceinline__ void mma16816(float* d, const uint32_t* a,
                                         uint32_t b0, uint32_t b1) {
    asm volatile(
        "mma.sync.aligned.m16n8k16.row.col.f32.f16.f16.f32 "
        "{%0,%1,%2,%3}, {%4,%5,%6,%7}, {%8,%9}, {%0,%1,%2,%3};"
        : "+f"(d[0]), "+f"(d[1]), "+f"(d[2]), "+f"(d[3])
        : "r"(a[0]), "r"(a[1]), "r"(a[2]), "r"(a[3]), "r"(b0), "r"(b1));
}

__device__ __forceinline__ void ldsm4(uint32_t* r, uint32_t addr) {
    asm volatile("ldmatrix.sync.aligned.m8n8.x4.shared.b16 {%0,%1,%2,%3}, [%4];"
                 : "=r"(r[0]), "=r"(r[1]), "=r"(r[2]), "=r"(r[3]) : "r"(addr));
}

__global__ void __launch_bounds__(NT, 1)
fp_kernel(float* __restrict__ out, const float* __restrict__ x,
          const float* __restrict__ W, const float* __restrict__ bias) {
    extern __shared__ char smem[];
    const uint32_t sW = smem_u32(smem);
    float* bs = reinterpret_cast<float*>(smem + SMEM_BOFF);
    uint32_t* zs = reinterpret_cast<uint32_t*>(smem + SMEM_ZOFF);

    const int tid = threadIdx.x, lane = tid & 31, warp = tid >> 5;
    const int g = lane >> 2, tig = lane & 3;

    // ---- stage W fp16 (512B rows, XOR swizzle) — identical to R5 -----------
    {
        const float2* W2 = reinterpret_cast<const float2*>(W);
        for (int idx = tid; idx < F * (F / 2); idx += NT) {
            const int n = idx >> 7;
            const float2 w = W2[idx];
            uint32_t off = (uint32_t)(n * 512 + (idx & 127) * 4);
            off ^= (uint32_t)((n & 7) << 4);
            *reinterpret_cast<__half2*>(smem + off) = __floats2half2_rn(w.x, w.y);
        }
        bs[tid] = bias[tid];
    }
    __syncthreads();            // the only block sync in the kernel

    // ---- geometry (identical to R5) ----------------------------------------
    const int n_lane = (lane & 7) + ((lane >> 4) << 3);
    const uint32_t lane_k = (uint32_t)(((lane >> 3) & 1) * 16);
    const uint32_t xorv = (uint32_t)((lane & 7) << 4);
    const uint32_t lbase = sW + (uint32_t)(n_lane * 512);
    const size_t m0 = (size_t)blockIdx.x * 128 + warp * 16 + g;
    const float* x0 = x + m0 * 256;
    const float* x1 = x0 + 8 * 256;
    float* o0 = out + m0 * 256;
    float* o1 = o0 + 8 * 256;

    uint32_t za[64];            // z A-fragments: [c 16][4]
    #pragma unroll
    for (int i = 0; i < 64; ++i) za[i] = 0u;

    #pragma unroll 1
    for (int it = 0; it < ITERS; ++it) {
        const bool last = (it == ITERS - 1);

        if (it) {               // reload own fragments (same-thread w->r)
            #pragma unroll
            for (int q = 0; q < 64; ++q)
                za[q] = zs[q * NT + tid];
        }

        #pragma unroll
        for (int nc = 0; nc < 4; ++nc) {            // 4 feat chunks of 64
            // ---- accumulator init: d = b + x (adds hide under GEMM) ---------
            float d[32];
            #pragma unroll
            for (int nt = 0; nt < 8; ++nt) {
                const int n = nc * 64 + nt * 8 + tig * 2;
                const float2 bb = *reinterpret_cast<const float2*>(bs + n);
                const float2 xa = *reinterpret_cast<const float2*>(x0 + n);
                const float2 xb = *reinterpret_cast<const float2*>(x1 + n);
                d[nt * 4 + 0] = bb.x + xa.x;    // (row g,   feat n)
                d[nt * 4 + 1] = bb.y + xa.y;    // (row g,   feat n+1)
                d[nt * 4 + 2] = bb.x + xb.x;    // (row g+8, feat n)
                d[nt * 4 + 3] = bb.y + xb.y;    // (row g+8, feat n+1)
            }

            if (it) {                               // it==0: z = 0, skip GEMM
                const uint32_t cb = lbase + (uint32_t)(nc * 64 * 512);
                uint32_t bf[2][16];
                #pragma unroll
                for (int ntp = 0; ntp < 4; ++ntp)   // preload k-tile 0
                    ldsm4(&bf[0][ntp * 4],
                          cb + (uint32_t)(ntp * 8192) + (lane_k ^ xorv));
                #pragma unroll
                for (int c = 0; c < 16; ++c) {
                    const int cur = c & 1;
                    if (c < 15) {                   // prefetch k-tile c+1
                        #pragma unroll
                        for (int ntp = 0; ntp < 4; ++ntp)
                            ldsm4(&bf[cur ^ 1][ntp * 4],
                                  cb + (uint32_t)(ntp * 8192)
                                     + ((lane_k + (uint32_t)((c + 1) * 32)) ^ xorv));
                    }
                    #pragma unroll
                    for (int nt = 0; nt < 8; ++nt) {
                        const int bi = (nt >> 1) * 4 + (nt & 1) * 2;
                        mma16816(&d[nt * 4], &za[c * 4],
                                 bf[cur][bi], bf[cur][bi + 1]);
                    }
                }
            }

            // ---- epilogue: z_new = tanh(d)  (b, x already inside d) ---------
            #pragma unroll
            for (int nt = 0; nt < 8; ++nt) {
                const int n = nc * 64 + nt * 8 + tig * 2;
                const float* dd = &d[nt * 4];
                const float t0 = tanh_approx(dd[0]);
                const float t1 = tanh_approx(dd[1]);
                const float t2 = tanh_approx(dd[2]);
                const float t3 = tanh_approx(dd[3]);
                if (!last) {
                    // feat n -> next-iter A k-tile (validated R5 remap)
                    const int ci = (nc * 4 + (nt >> 1)) * 4 + (nt & 1) * 2;
                    zs[ci * NT + tid]       = pack2(t0, t1);
                    zs[(ci + 1) * NT + tid] = pack2(t2, t3);
                } else {
                    *reinterpret_cast<float2*>(o0 + n) = make_float2(t0, t1);
                    *reinterpret_cast<float2*>(o1 + n) = make_float2(t2, t3);
                }
            }
        }
        // no barrier: each thread re-reads only its own zs slots next iter
    }
}

// ----------------------------------------------------------------------------
extern "C" void kernel_launch(void* const* d_in, const int* in_sizes, int n_in,
                              void* d_out, int out_size) {
    const float* x = nullptr;
    const float* W = nullptr;
    const float* b = nullptr;
    for (int i = 0; i < n_in; ++i) {
        if (in_sizes[i] == BATCH * F)   x = (const float*)d_in[i];
        else if (in_sizes[i] == F * F)  W = (const float*)d_in[i];
        else if (in_sizes[i] == F)      b = (const float*)d_in[i];
    }
    if (!x && n_in > 0) x = (const float*)d_in[0];
    if (!W && n_in > 1) W = (const float*)d_in[1];
    if (!b && n_in > 2) b = (const float*)d_in[2];

    static int once = 0;
    if (!once) {
        cudaFuncSetAttribute(fp_kernel,
                             cudaFuncAttributeMaxDynamicSharedMemorySize,
                             SMEM_TOTAL);
        once = 1;
    }
    fp_kernel<<<NB, NT, SMEM_TOTAL>>>((float*)d_out, x, W, b);
}